// round 14
// baseline (speedup 1.0000x reference)
#include <cuda_runtime.h>
#include <cuda_bf16.h>
#include <math.h>
#include <stdint.h>

// ---------------------------------------------------------------------------
// Problem constants
// ---------------------------------------------------------------------------
#define Bn    64
#define Tn    512
#define HIDn  512
#define Hn    256
#define G4n   1024           // 4*H
#define NLn   9
#define BTn   (Bn*Tn)        // 32768

typedef unsigned long long u64;

// ---------------------------------------------------------------------------
// Device scratch (cudaMalloc forbidden -> module globals)
// ---------------------------------------------------------------------------
__device__ float g_xA[BTn*HIDn];                  // 64 MB  (final layer output, fp32)
__device__ __nv_bfloat16 g_xh[BTn*HIDn];          // 32 MB  (bf16 GEMM A: emb / layer-0 h)
__device__ __nv_bfloat16 g_wh[2048*HIDn];         //  2 MB  (bf16 GEMM B = W_ih layer)
__device__ float g_xp[2ll*BTn*G4n];               // 256 MB [dir][bt][gate-row]
__device__ float g_logits[BTn*NLn];
__device__ float g_crf[Bn];

// ---------------------------------------------------------------------------
__device__ __forceinline__ float tanh_a(float x){
    float y; asm("tanh.approx.f32 %0, %1;" : "=f"(y) : "f"(x)); return y;
}
__device__ __forceinline__ float sigm_a(float x){
    return fmaf(0.5f, tanh_a(0.5f*x), 0.5f);
}

#define CP16(d, s) asm volatile("cp.async.cg.shared.global [%0], [%1], 16;" :: "r"(d), "l"(s))
#define CP_COMMIT() asm volatile("cp.async.commit_group;")

// ---------------------------------------------------------------------------
// Embedding gather directly to bf16: g_xh[bt][:] = bf16(emb[ids[bt]][:])
// ---------------------------------------------------------------------------
__global__ void embed_kernel(const int* __restrict__ ids,
                             const float* __restrict__ emb){
    int bt = blockIdx.x;
    int id = ids[bt];
    float4 v = reinterpret_cast<const float4*>(emb + (size_t)id * HIDn)[threadIdx.x];
    __nv_bfloat162 o0 = __floats2bfloat162_rn(v.x, v.y);
    __nv_bfloat162 o1 = __floats2bfloat162_rn(v.z, v.w);
    uint2 pk = make_uint2(*reinterpret_cast<uint32_t*>(&o0),
                          *reinterpret_cast<uint32_t*>(&o1));
    *reinterpret_cast<uint2*>(g_xh + (size_t)bt*HIDn + threadIdx.x*4) = pk;
}

// ---------------------------------------------------------------------------
// fp32 -> bf16 weight convert
// ---------------------------------------------------------------------------
__global__ __launch_bounds__(256)
void conv_w_kernel(const float* __restrict__ W){
    size_t i = (((size_t)blockIdx.x << 8) + threadIdx.x) << 3;
    float4 v0 = *reinterpret_cast<const float4*>(W + i);
    float4 v1 = *reinterpret_cast<const float4*>(W + i + 4);
    __nv_bfloat162 o[4];
    o[0] = __floats2bfloat162_rn(v0.x, v0.y);
    o[1] = __floats2bfloat162_rn(v0.z, v0.w);
    o[2] = __floats2bfloat162_rn(v1.x, v1.y);
    o[3] = __floats2bfloat162_rn(v1.z, v1.w);
    *reinterpret_cast<uint4*>(g_wh + i) = *reinterpret_cast<uint4*>(o);
}

// ---------------------------------------------------------------------------
// Input projection on tensor cores (bf16 mma.sync, fp32 accumulate):
// C(32768 x 2048) = A(32768x512) * W(2048x512)^T ; xp = C + bi + bh.
// cp.async 4-buffer pipeline (issue-ahead 2), ONE __syncthreads per k-iter.
// (unchanged — verified)
// ---------------------------------------------------------------------------
#define ASTR 40
#define ABUF 10240
#define GSM_TOTAL (8*ABUF)

__global__ __launch_bounds__(256, 2)
void gemm_xp_mma(const float* __restrict__ bi, const float* __restrict__ bh){
    extern __shared__ __align__(16) char gsm[];
    const uint32_t smb = (uint32_t)__cvta_generic_to_shared(gsm);

    const int tid  = threadIdx.x;
    const int wid  = tid >> 5;
    const int lane = tid & 31;
    const int m0 = blockIdx.y << 7;
    const int n0 = blockIdx.x << 7;
    const int wm = wid >> 2;
    const int wn = wid & 3;

    float acc[4][4][4];
    #pragma unroll
    for (int mi=0;mi<4;mi++)
        #pragma unroll
        for (int ni=0;ni<4;ni++)
            #pragma unroll
            for (int r=0;r<4;r++) acc[mi][ni][r]=0.f;

    const int lrow = tid >> 1;
    const int lqo  = (tid & 1) << 4;
    const __nv_bfloat16* gA = g_xh + (size_t)(m0 + lrow)*HIDn + lqo;
    const __nv_bfloat16* gB = g_wh + (size_t)(n0 + lrow)*HIDn + lqo;
    const uint32_t rowb = lrow*(ASTR*2) + lqo*2;

    uint32_t aRel[4], bRel[4];
    {
        int r16 = lane & 15;
        #pragma unroll
        for (int mi=0;mi<4;mi++)
            aRel[mi] = (((wm<<6) + (mi<<4) + r16)*ASTR + ((lane>>4) << 3)) * 2;
        #pragma unroll
        for (int ni=0;ni<4;ni++)
            bRel[ni] = (((wn<<5) + (ni<<3) + (r16 & 7))*ASTR + (((r16>>3)&1) << 3)) * 2;
    }

    #pragma unroll
    for (int s = 0; s < 2; ++s){
        uint32_t da = smb + (s&3)*ABUF + rowb;
        uint32_t db = smb + 4*ABUF + (s&3)*ABUF + rowb;
        const __nv_bfloat16* sa = gA + s*32;
        const __nv_bfloat16* sb = gB + s*32;
        CP16(da, sa); CP16(da+16, sa+8);
        CP16(db, sb); CP16(db+16, sb+8);
        CP_COMMIT();
    }

    for (int it = 0; it < 16; ++it){
        if (it < 14){
            int s = it + 2;
            uint32_t da = smb + (s&3)*ABUF + rowb;
            uint32_t db = smb + 4*ABUF + (s&3)*ABUF + rowb;
            const __nv_bfloat16* sa = gA + s*32;
            const __nv_bfloat16* sb = gB + s*32;
            CP16(da, sa); CP16(da+16, sa+8);
            CP16(db, sb); CP16(db+16, sb+8);
            CP_COMMIT();
            asm volatile("cp.async.wait_group 2;");
        } else {
            asm volatile("cp.async.wait_group 0;");
        }
        __syncthreads();

        const uint32_t aBase = smb + (it&3)*ABUF;
        const uint32_t bBase = smb + 4*ABUF + (it&3)*ABUF;
        #pragma unroll
        for (int kk = 0; kk < 2; ++kk){
            uint32_t af[4][4];
            #pragma unroll
            for (int mi=0;mi<4;mi++){
                asm volatile("ldmatrix.sync.aligned.m8n8.x4.shared.b16 "
                    "{%0,%1,%2,%3}, [%4];"
                    : "=r"(af[mi][0]),"=r"(af[mi][1]),"=r"(af[mi][2]),"=r"(af[mi][3])
                    : "r"(aBase + aRel[mi] + kk*32));
            }
            uint32_t bfr[4][2];
            #pragma unroll
            for (int ni=0;ni<4;ni++){
                asm volatile("ldmatrix.sync.aligned.m8n8.x2.shared.b16 "
                    "{%0,%1}, [%2];"
                    : "=r"(bfr[ni][0]),"=r"(bfr[ni][1])
                    : "r"(bBase + bRel[ni] + kk*32));
            }
            #pragma unroll
            for (int mi=0;mi<4;mi++){
                #pragma unroll
                for (int ni=0;ni<4;ni++){
                    asm volatile(
                        "mma.sync.aligned.m16n8k16.row.col.f32.bf16.bf16.f32 "
                        "{%0,%1,%2,%3}, {%4,%5,%6,%7}, {%8,%9}, {%0,%1,%2,%3};"
                        : "+f"(acc[mi][ni][0]),"+f"(acc[mi][ni][1]),
                          "+f"(acc[mi][ni][2]),"+f"(acc[mi][ni][3])
                        : "r"(af[mi][0]),"r"(af[mi][1]),"r"(af[mi][2]),"r"(af[mi][3]),
                          "r"(bfr[ni][0]),"r"(bfr[ni][1]));
                }
            }
        }
    }

    const int dir = n0 >> 10;
    #pragma unroll
    for (int ni=0;ni<4;ni++){
        int ncol = n0 + (wn<<5) + (ni<<3) + ((lane & 3) << 1);
        float bs0 = bi[ncol]   + bh[ncol];
        float bs1 = bi[ncol+1] + bh[ncol+1];
        int g = ncol & 1023;
        #pragma unroll
        for (int mi=0;mi<4;mi++){
            int mrow = m0 + (wm<<6) + (mi<<4) + (lane >> 2);
            float2 v0 = make_float2(acc[mi][ni][0] + bs0, acc[mi][ni][1] + bs1);
            float2 v1 = make_float2(acc[mi][ni][2] + bs0, acc[mi][ni][3] + bs1);
            *reinterpret_cast<float2*>(&g_xp[((size_t)dir*BTn + mrow)*G4n + g])   = v0;
            *reinterpret_cast<float2*>(&g_xp[((size_t)dir*BTn + mrow+8)*G4n + g]) = v1;
        }
    }
}

// ---------------------------------------------------------------------------
// Cluster-based persistent bidirectional LSTM — TWO INTERLEAVED CHAINS.
// 8 clusters x 8 CTAs; each cluster runs TWO independent batch-group chains
// (A, B). While chain A's DSMEM exchange + mbarrier arrivals are in flight,
// the CTA computes chain B's step (and vice versa) -> exchange latency hidden.
// W fragments (same dir) shared across chains in registers.
// Smem: WSTG[128][264]bf16 @0 | HBUF[ch2][ph2][8][264]bf16 @67584 |
//       GS[128][9]f32 @84480 | STAGE[2][8][32]bf16 @89088 | MB[4] @90112
// ---------------------------------------------------------------------------
#define HSTR 264
#define OFF_W 0
#define OFF_H 67584
#define OFF_G 84480
#define OFF_S 89088
#define OFF_MB 90112
#define LSTM_SMEM 90240
#define HPH 4224                 // bytes per phase buffer (8*264*2)
#define HCH 8448                 // bytes per chain (2 phases)

__global__ __launch_bounds__(256, 1) __cluster_dims__(8, 1, 1)
void lstm_cluster_kernel(int layer, const float* __restrict__ whh){
    extern __shared__ __align__(16) char sm[];

    const int tid  = threadIdx.x;
    const int wid  = tid >> 5;
    const int lane = tid & 31;
    const int rank = blockIdx.x & 7;
    const int cid  = blockIdx.x >> 3;      // 0..7
    const int dir  = cid & 1;
    const int bpair = cid >> 1;            // 0..3 (two bgrps per cluster)
    const int u0   = rank << 5;

    const uint32_t smb = (uint32_t)__cvta_generic_to_shared(sm);

    // stage W_hh (fp32->bf16) into smem: row r = gate*32+uu (R10/R12 order)
    for (int idx = tid; idx < 128*64; idx += 256){
        int r  = idx >> 6;
        int kq = (idx & 63) << 2;
        int grow = dir*G4n + (r>>5)*Hn + u0 + (r&31);
        float4 v = *reinterpret_cast<const float4*>(whh + (size_t)grow*Hn + kq);
        __nv_bfloat162 o0 = __floats2bfloat162_rn(v.x, v.y);
        __nv_bfloat162 o1 = __floats2bfloat162_rn(v.z, v.w);
        uint2 pk = make_uint2(*reinterpret_cast<uint32_t*>(&o0),
                              *reinterpret_cast<uint32_t*>(&o1));
        *reinterpret_cast<uint2*>(sm + OFF_W + r*(HSTR*2) + kq*2) = pk;
    }
    // zero all 4 h buffers (2 chains x 2 phases)
    for (int i = tid; i < 4*8*HSTR; i += 256)
        *reinterpret_cast<__nv_bfloat16*>(sm + OFF_H + i*2) = __nv_bfloat16(0.f);

    // init 4 mbarriers (chain*2+phase), count = 8 arrivals
    if (tid == 0){
        #pragma unroll
        for (int j = 0; j < 4; ++j)
            asm volatile("mbarrier.init.shared.b64 [%0], %1;"
                         :: "r"(smb + OFF_MB + j*8), "r"(8) : "memory");
    }
    __syncthreads();

    // preload W fragments into registers: warp w -> gate rows 16w..16w+15
    uint32_t afr[16][4];
    {
        uint32_t aAddr = smb + OFF_W + (wid*16 + (lane & 15))*(HSTR*2)
                       + (((lane >> 4) << 3) << 1);
        #pragma unroll
        for (int kk = 0; kk < 16; ++kk){
            asm volatile("ldmatrix.sync.aligned.m8n8.x4.shared.b16 "
                "{%0,%1,%2,%3}, [%4];"
                : "=r"(afr[kk][0]),"=r"(afr[kk][1]),"=r"(afr[kk][2]),"=r"(afr[kk][3])
                : "r"(aAddr + kk*32));
        }
    }

    const int r16 = lane & 15;
    const uint32_t bRow = smb + OFF_H + (r16 & 7)*(HSTR*2) + (((r16>>3)&1) << 4);

    const int bb = tid >> 5;          // elementwise batch (per-warp constant)
    const int uu = tid & 31;          // elementwise unit (consecutive in warp)
    float c_reg[2] = {0.f, 0.f};
    int bglob[2];
    bglob[0] = ((bpair<<1)     << 3) + bb;
    bglob[1] = ((bpair<<1) + 1 << 3) + bb;   // ((bpair*2+1)<<3)+bb

    float* gs = reinterpret_cast<float*>(sm + OFF_G);
    const int grow0 = wid*16 + (lane >> 2);
    const int gcol0 = (lane & 3) << 1;

    // h zero + mbarrier init visible cluster-wide before any remote traffic
    asm volatile("barrier.cluster.arrive.aligned;" ::: "memory");
    asm volatile("barrier.cluster.wait.aligned;"   ::: "memory");

    // xp bases + step-0 prefetch for both chains
    const float* xp0[2];
    float xg[2][4];
    #pragma unroll
    for (int ch = 0; ch < 2; ++ch){
        xp0[ch] = g_xp + ((size_t)dir*BTn + (size_t)bglob[ch]*Tn)*G4n + u0 + uu;
        const float* x = xp0[ch] + (size_t)(dir ? (Tn-1) : 0)*G4n;
        xg[ch][0] = __ldcs(x);     xg[ch][1] = __ldcs(x+256);
        xg[ch][2] = __ldcs(x+512); xg[ch][3] = __ldcs(x+768);
    }

    for (int step = 0; step < Tn; ++step){
        const int t = dir ? (Tn-1-step) : step;
        const int p = step & 1;
        const int q = p ^ 1;
        // parity for mb[*][p] at this step (both chains identical schedule)
        int par = (step >> 1) & 1;
        if (p == 0) par ^= 1;

        #pragma unroll
        for (int ch = 0; ch < 2; ++ch){
            // wait for this chain's h(step) (first step: zero-init, no wait)
            if (step > 0){
                uint32_t mba = smb + OFF_MB + (uint32_t)((ch<<1) + p)*8;
                asm volatile(
                    "{\n\t.reg .pred P;\n\t"
                    "LW%=:\n\t"
                    "mbarrier.try_wait.parity.acquire.cluster.shared::cta.b64 P, [%0], %1, 0x989680;\n\t"
                    "@P bra LD%=;\n\t"
                    "bra LW%=;\n\t"
                    "LD%=:\n\t}"
                    :: "r"(mba), "r"(par) : "memory");
            }

            // prefetch next step's xp for this chain (consumed next superstep)
            float ng0=0.f, ng1=0.f, ng2=0.f, ng3=0.f;
            if (step+1 < Tn){
                const float* x = xp0[ch] + (size_t)(dir ? (Tn-2-step) : (step+1))*G4n;
                ng0 = __ldcs(x);     ng1 = __ldcs(x+256);
                ng2 = __ldcs(x+512); ng3 = __ldcs(x+768);
            }

            // gates = W(regs) @ h(smem): batch all 16 ldmatrix, then 16 mmas
            float d[4][4];
            #pragma unroll
            for (int j=0;j<4;j++){ d[j][0]=0.f; d[j][1]=0.f; d[j][2]=0.f; d[j][3]=0.f; }
            {
                const uint32_t bA = bRow + (uint32_t)ch*HCH + (uint32_t)p*HPH;
                uint32_t bfrag[16][2];
                #pragma unroll
                for (int kk = 0; kk < 16; ++kk){
                    asm volatile("ldmatrix.sync.aligned.m8n8.x2.shared.b16 "
                        "{%0,%1}, [%2];" : "=r"(bfrag[kk][0]),"=r"(bfrag[kk][1])
                        : "r"(bA + kk*32));
                }
                #pragma unroll
                for (int kk = 0; kk < 16; ++kk){
                    float* dj = d[kk & 3];
                    asm volatile(
                        "mma.sync.aligned.m16n8k16.row.col.f32.bf16.bf16.f32 "
                        "{%0,%1,%2,%3}, {%4,%5,%6,%7}, {%8,%9}, {%0,%1,%2,%3};"
                        : "+f"(dj[0]),"+f"(dj[1]),"+f"(dj[2]),"+f"(dj[3])
                        : "r"(afr[kk][0]),"r"(afr[kk][1]),"r"(afr[kk][2]),"r"(afr[kk][3]),
                          "r"(bfrag[kk][0]),"r"(bfrag[kk][1]));
                }
            }
            gs[grow0*9     + gcol0]     = (d[0][0]+d[1][0]) + (d[2][0]+d[3][0]);
            gs[grow0*9     + gcol0 + 1] = (d[0][1]+d[1][1]) + (d[2][1]+d[3][1]);
            gs[(grow0+8)*9 + gcol0]     = (d[0][2]+d[1][2]) + (d[2][2]+d[3][2]);
            gs[(grow0+8)*9 + gcol0 + 1] = (d[0][3]+d[1][3]) + (d[2][3]+d[3][3]);
            __syncthreads();

            // elementwise (tanh.approx; c stays in register)
            float gi = gs[uu*9      + bb] + xg[ch][0];
            float gf = gs[(32+uu)*9 + bb] + xg[ch][1];
            float gg = gs[(64+uu)*9 + bb] + xg[ch][2];
            float go = gs[(96+uu)*9 + bb] + xg[ch][3];
            c_reg[ch] = sigm_a(gf)*c_reg[ch] + sigm_a(gi)*tanh_a(gg);
            float hh = sigm_a(go)*tanh_a(c_reg[ch]);

            if (step + 1 < Tn){
                *reinterpret_cast<__nv_bfloat16*>(sm + OFF_S + ch*512 + bb*64 + uu*2)
                    = __float2bfloat16_rn(hh);
                __syncthreads();

                // distribute my 32-unit h slice to all 8 CTAs' next-phase buffer
                {
                    int rr = tid >> 5;
                    int j  = tid & 31;
                    int sb2 = j >> 2;
                    int gq  = j & 3;
                    u64 w0 = *reinterpret_cast<const u64*>(sm + OFF_S + ch*512 + sb2*64 + gq*16);
                    u64 w1 = *reinterpret_cast<const u64*>(sm + OFF_S + ch*512 + sb2*64 + gq*16 + 8);
                    uint32_t la = smb + OFF_H + (uint32_t)ch*HCH + (uint32_t)q*HPH
                                + sb2*(HSTR*2) + (u0<<1) + (gq<<4);
                    uint32_t ra;
                    asm volatile("mapa.shared::cluster.u32 %0, %1, %2;"
                                 : "=r"(ra) : "r"(la), "r"(rr));
                    asm volatile("st.shared::cluster.b64 [%0], %1;" :: "r"(ra),   "l"(w0));
                    asm volatile("st.shared::cluster.b64 [%0], %1;" :: "r"(ra+8), "l"(w1));
                }
                __syncthreads();     // all pushes issued before representatives arrive

                // arrive (release, cluster) on every rank's mb[ch][q]
                if (tid < 8){
                    uint32_t la = smb + OFF_MB + (uint32_t)((ch<<1) + q)*8;
                    uint32_t ra;
                    asm volatile("mapa.shared::cluster.u32 %0, %1, %2;"
                                 : "=r"(ra) : "r"(la), "r"(tid));
                    asm volatile("mbarrier.arrive.release.cluster.shared::cluster.b64 _, [%0];"
                                 :: "r"(ra) : "memory");
                }
            } else {
                __syncthreads();     // separate chains' shared gs usage at final step
            }

            // global h store (fire-and-forget; overlaps next chain's compute)
            if (layer == 0){
                g_xh[((size_t)bglob[ch]*Tn + t)*HIDn + dir*Hn + u0 + uu]
                    = __float2bfloat16_rn(hh);
            } else {
                g_xA[((size_t)bglob[ch]*Tn + t)*HIDn + dir*Hn + u0 + uu] = hh;
            }

            xg[ch][0] = ng0; xg[ch][1] = ng1; xg[ch][2] = ng2; xg[ch][3] = ng3;
        }
    }
}

// ---------------------------------------------------------------------------
// Logits: logits[bt][l] = x[bt][:] . cls_w[l][:] + cls_b[l]   (warp per row)
// ---------------------------------------------------------------------------
__global__ __launch_bounds__(256)
void logits_kernel(const float* __restrict__ cls_w, const float* __restrict__ cls_b){
    int row  = (blockIdx.x << 3) + (threadIdx.x >> 5);
    int lane = threadIdx.x & 31;
    const float* xr = g_xA + (size_t)row*HIDn + lane*16;
    float xv[16];
    #pragma unroll
    for (int q=0;q<4;q++){
        float4 v = *reinterpret_cast<const float4*>(xr + q*4);
        xv[q*4+0]=v.x; xv[q*4+1]=v.y; xv[q*4+2]=v.z; xv[q*4+3]=v.w;
    }
    float myout = 0.f;
    #pragma unroll
    for (int l=0;l<NLn;l++){
        const float* wr = cls_w + l*HIDn + lane*16;
        float p = 0.f;
        #pragma unroll
        for (int j=0;j<16;j++) p = fmaf(xv[j], __ldg(wr+j), p);
        #pragma unroll
        for (int o=16;o;o>>=1) p += __shfl_xor_sync(0xffffffffu, p, o);
        if (lane == l) myout = p + cls_b[l];
    }
    if (lane < NLn) g_logits[(size_t)row*NLn + lane] = myout;
}

// ---------------------------------------------------------------------------
// CRF: one warp per batch element. lanes 0..8 hold states.
// ---------------------------------------------------------------------------
__global__ void crf_kernel(const int* __restrict__ labels,
                           const float* __restrict__ start_trans,
                           const float* __restrict__ end_trans,
                           const float* __restrict__ trans){
    int b    = blockIdx.x;
    int lane = threadIdx.x;
    __shared__ float tr_s[NLn*NLn];
    for (int i = lane; i < NLn*NLn; i += 32) tr_s[i] = trans[i];
    __syncwarp();

    bool act = lane < NLn;
    float tr[NLn];
    #pragma unroll
    for (int k=0;k<NLn;k++) tr[k] = act ? trans[k*NLn + lane] : 0.f;

    const float* lg = g_logits + (size_t)b*Tn*NLn;
    const int*   lb = labels   + (size_t)b*Tn;

    float em    = act ? lg[lane] : -1e30f;
    float alpha = act ? (start_trans[lane] + em) : -1e30f;
    int prev = lb[0];
    float num = __shfl_sync(0xffffffffu, em, prev) + start_trans[prev];

    for (int t=1;t<Tn;t++){
        em = act ? lg[t*NLn + lane] : -1e30f;
        int tag = lb[t];
        float v[NLn], m = -1e30f;
        #pragma unroll
        for (int k=0;k<NLn;k++){
            float ak = __shfl_sync(0xffffffffu, alpha, k);
            v[k] = ak + tr[k];
            m = fmaxf(m, v[k]);
        }
        float s = 0.f;
        #pragma unroll
        for (int k=0;k<NLn;k++) s += __expf(v[k]-m);
        float na = m + __logf(s) + em;
        num += tr_s[prev*NLn + tag] + __shfl_sync(0xffffffffu, em, tag);
        alpha = act ? na : -1e30f;
        prev = tag;
    }
    float fa = act ? (alpha + end_trans[lane]) : -1e30f;
    float m = fa;
    #pragma unroll
    for (int o=16;o;o>>=1) m = fmaxf(m, __shfl_xor_sync(0xffffffffu, m, o));
    float s = act ? __expf(fa - m) : 0.f;
    #pragma unroll
    for (int o=16;o;o>>=1) s += __shfl_xor_sync(0xffffffffu, s, o);
    float denom = m + __logf(s);
    num += end_trans[prev];
    if (lane == 0) g_crf[b] = num - denom;
}

__global__ void finish_kernel(float* out){
    int lane = threadIdx.x;
    float s = g_crf[lane] + g_crf[lane+32];
    #pragma unroll
    for (int o=16;o;o>>=1) s += __shfl_xor_sync(0xffffffffu, s, o);
    if (lane == 0) out[0] = -s;
}

// ---------------------------------------------------------------------------
extern "C" void kernel_launch(void* const* d_in, const int* in_sizes, int n_in,
                              void* d_out, int out_size){
    const int*   ids         = (const int*)  d_in[0];
    const int*   labels      = (const int*)  d_in[1];
    const float* emb         = (const float*)d_in[2];
    const float* w_ih        = (const float*)d_in[3];
    const float* w_hh        = (const float*)d_in[4];
    const float* b_ih        = (const float*)d_in[5];
    const float* b_hh        = (const float*)d_in[6];
    const float* cls_w       = (const float*)d_in[7];
    const float* cls_b       = (const float*)d_in[8];
    const float* start_trans = (const float*)d_in[9];
    const float* end_trans   = (const float*)d_in[10];
    const float* trans       = (const float*)d_in[11];
    float* out = (float*)d_out;

    cudaFuncSetAttribute(lstm_cluster_kernel,
                         cudaFuncAttributeMaxDynamicSharedMemorySize, LSTM_SMEM);
    cudaFuncSetAttribute(gemm_xp_mma,
                         cudaFuncAttributeMaxDynamicSharedMemorySize, GSM_TOTAL);

    embed_kernel<<<BTn,128>>>(ids, emb);

    for (int layer = 0; layer < 2; ++layer){
        conv_w_kernel<<<(2048*HIDn)/2048, 256>>>(w_ih + (size_t)layer*2048*HIDn);
        gemm_xp_mma<<<dim3(16,256),256,GSM_TOTAL>>>(
            b_ih + (size_t)layer*2048,
            b_hh + (size_t)layer*2048);
        lstm_cluster_kernel<<<64,256,LSTM_SMEM>>>(layer,
            w_hh + (size_t)layer*2*G4n*Hn);
    }

    logits_kernel<<<BTn/8,256>>>(cls_w, cls_b);
    crf_kernel<<<Bn,32>>>(labels, start_trans, end_trans, trans);
    finish_kernel<<<1,32>>>(out);
}

// round 16
// speedup vs baseline: 1.3603x; 1.3603x over previous
#include <cuda_runtime.h>
#include <cuda_bf16.h>
#include <math.h>
#include <stdint.h>

// ---------------------------------------------------------------------------
// Problem constants
// ---------------------------------------------------------------------------
#define Bn    64
#define Tn    512
#define HIDn  512
#define Hn    256
#define G4n   1024           // 4*H
#define NLn   9
#define BTn   (Bn*Tn)        // 32768

typedef unsigned long long u64;

// ---------------------------------------------------------------------------
// Device scratch (cudaMalloc forbidden -> module globals)
// ---------------------------------------------------------------------------
__device__ float g_xA[BTn*HIDn];                  // 64 MB  (final layer output, fp32)
__device__ __nv_bfloat16 g_xh[BTn*HIDn];          // 32 MB  (bf16 GEMM A: emb / layer-0 h)
__device__ __nv_bfloat16 g_wh[2048*HIDn];         //  2 MB  (bf16 GEMM B = W_ih layer)
__device__ float g_xp[2ll*BTn*G4n];               // 256 MB [dir][bt][gate-row]
__device__ float g_logits[BTn*NLn];
__device__ float g_crf[Bn];

// ---------------------------------------------------------------------------
__device__ __forceinline__ float tanh_a(float x){
    float y; asm("tanh.approx.f32 %0, %1;" : "=f"(y) : "f"(x)); return y;
}
__device__ __forceinline__ float sigm_a(float x){
    return fmaf(0.5f, tanh_a(0.5f*x), 0.5f);
}

#define CP16(d, s) asm volatile("cp.async.cg.shared.global [%0], [%1], 16;" :: "r"(d), "l"(s))
#define CP_COMMIT() asm volatile("cp.async.commit_group;")

// ---------------------------------------------------------------------------
// Embedding gather directly to bf16: g_xh[bt][:] = bf16(emb[ids[bt]][:])
// ---------------------------------------------------------------------------
__global__ void embed_kernel(const int* __restrict__ ids,
                             const float* __restrict__ emb){
    int bt = blockIdx.x;
    int id = ids[bt];
    float4 v = reinterpret_cast<const float4*>(emb + (size_t)id * HIDn)[threadIdx.x];
    __nv_bfloat162 o0 = __floats2bfloat162_rn(v.x, v.y);
    __nv_bfloat162 o1 = __floats2bfloat162_rn(v.z, v.w);
    uint2 pk = make_uint2(*reinterpret_cast<uint32_t*>(&o0),
                          *reinterpret_cast<uint32_t*>(&o1));
    *reinterpret_cast<uint2*>(g_xh + (size_t)bt*HIDn + threadIdx.x*4) = pk;
}

// ---------------------------------------------------------------------------
// fp32 -> bf16 weight convert
// ---------------------------------------------------------------------------
__global__ __launch_bounds__(256)
void conv_w_kernel(const float* __restrict__ W){
    size_t i = (((size_t)blockIdx.x << 8) + threadIdx.x) << 3;
    float4 v0 = *reinterpret_cast<const float4*>(W + i);
    float4 v1 = *reinterpret_cast<const float4*>(W + i + 4);
    __nv_bfloat162 o[4];
    o[0] = __floats2bfloat162_rn(v0.x, v0.y);
    o[1] = __floats2bfloat162_rn(v0.z, v0.w);
    o[2] = __floats2bfloat162_rn(v1.x, v1.y);
    o[3] = __floats2bfloat162_rn(v1.z, v1.w);
    *reinterpret_cast<uint4*>(g_wh + i) = *reinterpret_cast<uint4*>(o);
}

// ---------------------------------------------------------------------------
// Input projection on tensor cores (bf16 mma.sync, fp32 accumulate):
// C(32768 x 2048) = A(32768x512) * W(2048x512)^T ; xp = C + bi + bh.
// R14: 4 warps (128 thr), 2x2 warp grid, 64x64 warp tiles; B loaded via
// ldmatrix.x4 (two n8 frags per LDSM) -> 0.5 LDSM/mma; 2 CTAs/SM on regs.
// cp.async 4-buffer pipeline (issue-ahead 2), one __syncthreads per k-iter.
// ---------------------------------------------------------------------------
#define ASTR 40
#define ABUF 10240
#define GSM_TOTAL (8*ABUF)

__global__ __launch_bounds__(128, 2)
void gemm_xp_mma(const float* __restrict__ bi, const float* __restrict__ bh){
    extern __shared__ __align__(16) char gsm[];
    const uint32_t smb = (uint32_t)__cvta_generic_to_shared(gsm);

    const int tid  = threadIdx.x;
    const int wid  = tid >> 5;
    const int lane = tid & 31;
    const int m0 = blockIdx.y << 7;
    const int n0 = blockIdx.x << 7;
    const int wm = wid >> 1;          // 0..1
    const int wn = wid & 1;           // 0..1

    float acc[4][8][4];
    #pragma unroll
    for (int mi=0;mi<4;mi++)
        #pragma unroll
        for (int nj=0;nj<8;nj++)
            #pragma unroll
            for (int r=0;r<4;r++) acc[mi][nj][r]=0.f;

    // G->S: thread covers one full 64B row (32 bf16) of each buffer per stage
    const __nv_bfloat16* gA = g_xh + (size_t)(m0 + tid)*HIDn;
    const __nv_bfloat16* gB = g_wh + (size_t)(n0 + tid)*HIDn;
    const uint32_t rowb = tid*(ASTR*2);

    // ldmatrix byte offsets inside a buffer
    uint32_t aRel[4], bRel[4];
    {
        #pragma unroll
        for (int mi=0;mi<4;mi++)
            aRel[mi] = (((wm<<6) + (mi<<4) + (lane & 15))*ASTR + ((lane>>4) << 3)) * 2;
        #pragma unroll
        for (int nb=0;nb<4;nb++)
            bRel[nb] = (((wn<<6) + (nb<<4) + (lane & 7) + (((lane>>4)&1) << 3))*ASTR
                        + (((lane>>3)&1) << 3)) * 2;
    }

    // pipeline prologue: stages 0,1
    #pragma unroll
    for (int s = 0; s < 2; ++s){
        uint32_t da = smb + (s&3)*ABUF + rowb;
        uint32_t db = smb + 4*ABUF + (s&3)*ABUF + rowb;
        const __nv_bfloat16* sa = gA + s*32;
        const __nv_bfloat16* sb = gB + s*32;
        CP16(da,    sa);      CP16(da+16, sa+8);
        CP16(da+32, sa+16);   CP16(da+48, sa+24);
        CP16(db,    sb);      CP16(db+16, sb+8);
        CP16(db+32, sb+16);   CP16(db+48, sb+24);
        CP_COMMIT();
    }

    for (int it = 0; it < 16; ++it){
        if (it < 14){
            int s = it + 2;
            uint32_t da = smb + (s&3)*ABUF + rowb;
            uint32_t db = smb + 4*ABUF + (s&3)*ABUF + rowb;
            const __nv_bfloat16* sa = gA + s*32;
            const __nv_bfloat16* sb = gB + s*32;
            CP16(da,    sa);      CP16(da+16, sa+8);
            CP16(da+32, sa+16);   CP16(da+48, sa+24);
            CP16(db,    sb);      CP16(db+16, sb+8);
            CP16(db+32, sb+16);   CP16(db+48, sb+24);
            CP_COMMIT();
            asm volatile("cp.async.wait_group 2;");
        } else {
            asm volatile("cp.async.wait_group 0;");
        }
        __syncthreads();

        const uint32_t aBase = smb + (it&3)*ABUF;
        const uint32_t bBase = smb + 4*ABUF + (it&3)*ABUF;
        #pragma unroll
        for (int kk = 0; kk < 2; ++kk){
            uint32_t af[4][4];
            #pragma unroll
            for (int mi=0;mi<4;mi++){
                asm volatile("ldmatrix.sync.aligned.m8n8.x4.shared.b16 "
                    "{%0,%1,%2,%3}, [%4];"
                    : "=r"(af[mi][0]),"=r"(af[mi][1]),"=r"(af[mi][2]),"=r"(af[mi][3])
                    : "r"(aBase + aRel[mi] + kk*32));
            }
            uint32_t bfr[4][4];      // [nb][4]: regs 0,1 = n8 tile 2nb; 2,3 = 2nb+1
            #pragma unroll
            for (int nb=0;nb<4;nb++){
                asm volatile("ldmatrix.sync.aligned.m8n8.x4.shared.b16 "
                    "{%0,%1,%2,%3}, [%4];"
                    : "=r"(bfr[nb][0]),"=r"(bfr[nb][1]),"=r"(bfr[nb][2]),"=r"(bfr[nb][3])
                    : "r"(bBase + bRel[nb] + kk*32));
            }
            #pragma unroll
            for (int mi=0;mi<4;mi++){
                #pragma unroll
                for (int nb=0;nb<4;nb++){
                    asm volatile(
                        "mma.sync.aligned.m16n8k16.row.col.f32.bf16.bf16.f32 "
                        "{%0,%1,%2,%3}, {%4,%5,%6,%7}, {%8,%9}, {%0,%1,%2,%3};"
                        : "+f"(acc[mi][2*nb][0]),"+f"(acc[mi][2*nb][1]),
                          "+f"(acc[mi][2*nb][2]),"+f"(acc[mi][2*nb][3])
                        : "r"(af[mi][0]),"r"(af[mi][1]),"r"(af[mi][2]),"r"(af[mi][3]),
                          "r"(bfr[nb][0]),"r"(bfr[nb][1]));
                    asm volatile(
                        "mma.sync.aligned.m16n8k16.row.col.f32.bf16.bf16.f32 "
                        "{%0,%1,%2,%3}, {%4,%5,%6,%7}, {%8,%9}, {%0,%1,%2,%3};"
                        : "+f"(acc[mi][2*nb+1][0]),"+f"(acc[mi][2*nb+1][1]),
                          "+f"(acc[mi][2*nb+1][2]),"+f"(acc[mi][2*nb+1][3])
                        : "r"(af[mi][0]),"r"(af[mi][1]),"r"(af[mi][2]),"r"(af[mi][3]),
                          "r"(bfr[nb][2]),"r"(bfr[nb][3]));
                }
            }
        }
    }

    const int dir = n0 >> 10;
    #pragma unroll
    for (int nj=0;nj<8;nj++){
        int ncol = n0 + (wn<<6) + (nj<<3) + ((lane & 3) << 1);
        float bs0 = bi[ncol]   + bh[ncol];
        float bs1 = bi[ncol+1] + bh[ncol+1];
        int g = ncol & 1023;
        #pragma unroll
        for (int mi=0;mi<4;mi++){
            int mrow = m0 + (wm<<6) + (mi<<4) + (lane >> 2);
            float2 v0 = make_float2(acc[mi][nj][0] + bs0, acc[mi][nj][1] + bs1);
            float2 v1 = make_float2(acc[mi][nj][2] + bs0, acc[mi][nj][3] + bs1);
            *reinterpret_cast<float2*>(&g_xp[((size_t)dir*BTn + mrow)*G4n + g])   = v0;
            *reinterpret_cast<float2*>(&g_xp[((size_t)dir*BTn + mrow+8)*G4n + g]) = v1;
        }
    }
}

// ---------------------------------------------------------------------------
// Cluster-based persistent bidirectional LSTM — exact R12 (best: 797us/layer).
// Smem: WSTG[128][264]bf16 @0 | HBUF[2][8][264]bf16 @67584 | GS[128][9]f32
// @76032 | STAGE[8][32]bf16 @80640 | MB[2] @81152
// ---------------------------------------------------------------------------
#define HSTR 264
#define OFF_W 0
#define OFF_H 67584
#define OFF_G 76032
#define OFF_S 80640
#define OFF_MB 81152
#define LSTM_SMEM 81280
#define HPH 4224

__global__ __launch_bounds__(256, 1) __cluster_dims__(8, 1, 1)
void lstm_cluster_kernel(int layer, const float* __restrict__ whh){
    extern __shared__ __align__(16) char sm[];

    const int tid  = threadIdx.x;
    const int wid  = tid >> 5;
    const int lane = tid & 31;
    const int rank = blockIdx.x & 7;
    const int cid  = blockIdx.x >> 3;
    const int dir  = cid & 1;
    const int bgrp = cid >> 1;
    const int u0   = rank << 5;

    const uint32_t smb = (uint32_t)__cvta_generic_to_shared(sm);

    // stage W_hh (fp32->bf16) into smem: row r = gate*32+uu
    for (int idx = tid; idx < 128*64; idx += 256){
        int r  = idx >> 6;
        int kq = (idx & 63) << 2;
        int grow = dir*G4n + (r>>5)*Hn + u0 + (r&31);
        float4 v = *reinterpret_cast<const float4*>(whh + (size_t)grow*Hn + kq);
        __nv_bfloat162 o0 = __floats2bfloat162_rn(v.x, v.y);
        __nv_bfloat162 o1 = __floats2bfloat162_rn(v.z, v.w);
        uint2 pk = make_uint2(*reinterpret_cast<uint32_t*>(&o0),
                              *reinterpret_cast<uint32_t*>(&o1));
        *reinterpret_cast<uint2*>(sm + OFF_W + r*(HSTR*2) + kq*2) = pk;
    }
    for (int i = tid; i < 2*8*HSTR; i += 256)
        *reinterpret_cast<__nv_bfloat16*>(sm + OFF_H + i*2) = __nv_bfloat16(0.f);

    if (tid == 0){
        asm volatile("mbarrier.init.shared.b64 [%0], %1;" :: "r"(smb+OFF_MB),   "r"(8) : "memory");
        asm volatile("mbarrier.init.shared.b64 [%0], %1;" :: "r"(smb+OFF_MB+8), "r"(8) : "memory");
    }
    __syncthreads();

    // preload W fragments into registers: warp w -> gate rows 16w..16w+15
    uint32_t afr[16][4];
    {
        uint32_t aAddr = smb + OFF_W + (wid*16 + (lane & 15))*(HSTR*2)
                       + (((lane >> 4) << 3) << 1);
        #pragma unroll
        for (int kk = 0; kk < 16; ++kk){
            asm volatile("ldmatrix.sync.aligned.m8n8.x4.shared.b16 "
                "{%0,%1,%2,%3}, [%4];"
                : "=r"(afr[kk][0]),"=r"(afr[kk][1]),"=r"(afr[kk][2]),"=r"(afr[kk][3])
                : "r"(aAddr + kk*32));
        }
    }

    const int r16 = lane & 15;
    const uint32_t bBase = smb + OFF_H + (r16 & 7)*(HSTR*2) + (((r16>>3)&1) << 4);

    const int bb = tid >> 5;
    const int uu = tid & 31;
    const int bglob = (bgrp << 3) + bb;
    float c_reg = 0.f;

    float* gs = reinterpret_cast<float*>(sm + OFF_G);
    const int grow0 = wid*16 + (lane >> 2);
    const int gcol0 = (lane & 3) << 1;

    asm volatile("barrier.cluster.arrive.aligned;" ::: "memory");
    asm volatile("barrier.cluster.wait.aligned;"   ::: "memory");

    const float* xp0 = g_xp + ((size_t)dir*BTn + (size_t)bglob*Tn)*G4n + u0 + uu;
    float xgi, xgf, xgg, xgo;
    {
        const float* x = xp0 + (size_t)(dir ? (Tn-1) : 0)*G4n;
        xgi = __ldcs(x); xgf = __ldcs(x+256); xgg = __ldcs(x+512); xgo = __ldcs(x+768);
    }

    int ph0 = 0, ph1 = 0;

    for (int step = 0; step < Tn; ++step){
        const int t = dir ? (Tn-1-step) : step;
        const int p = step & 1;
        const int q = p ^ 1;

        float ngi=0.f, ngf=0.f, ngg=0.f, ngo=0.f;
        if (step+1 < Tn){
            const float* x = xp0 + (size_t)(dir ? (Tn-2-step) : (step+1))*G4n;
            ngi = __ldcs(x); ngf = __ldcs(x+256); ngg = __ldcs(x+512); ngo = __ldcs(x+768);
        }

        // gates = W(regs) @ h(smem): batch ALL 16 ldmatrix, then 16 mmas
        float d[4][4];
        #pragma unroll
        for (int j=0;j<4;j++){ d[j][0]=0.f; d[j][1]=0.f; d[j][2]=0.f; d[j][3]=0.f; }
        {
            const uint32_t bA = bBase + (uint32_t)p*HPH;
            uint32_t bfrag[16][2];
            #pragma unroll
            for (int kk = 0; kk < 16; ++kk){
                asm volatile("ldmatrix.sync.aligned.m8n8.x2.shared.b16 "
                    "{%0,%1}, [%2];" : "=r"(bfrag[kk][0]),"=r"(bfrag[kk][1])
                    : "r"(bA + kk*32));
            }
            #pragma unroll
            for (int kk = 0; kk < 16; ++kk){
                float* dj = d[kk & 3];
                asm volatile(
                    "mma.sync.aligned.m16n8k16.row.col.f32.bf16.bf16.f32 "
                    "{%0,%1,%2,%3}, {%4,%5,%6,%7}, {%8,%9}, {%0,%1,%2,%3};"
                    : "+f"(dj[0]),"+f"(dj[1]),"+f"(dj[2]),"+f"(dj[3])
                    : "r"(afr[kk][0]),"r"(afr[kk][1]),"r"(afr[kk][2]),"r"(afr[kk][3]),
                      "r"(bfrag[kk][0]),"r"(bfrag[kk][1]));
            }
        }
        gs[grow0*9     + gcol0]     = (d[0][0]+d[1][0]) + (d[2][0]+d[3][0]);
        gs[grow0*9     + gcol0 + 1] = (d[0][1]+d[1][1]) + (d[2][1]+d[3][1]);
        gs[(grow0+8)*9 + gcol0]     = (d[0][2]+d[1][2]) + (d[2][2]+d[3][2]);
        gs[(grow0+8)*9 + gcol0 + 1] = (d[0][3]+d[1][3]) + (d[2][3]+d[3][3]);
        __syncthreads();

        float gi = gs[uu*9      + bb] + xgi;
        float gf = gs[(32+uu)*9 + bb] + xgf;
        float gg = gs[(64+uu)*9 + bb] + xgg;
        float go = gs[(96+uu)*9 + bb] + xgo;
        c_reg = sigm_a(gf)*c_reg + sigm_a(gi)*tanh_a(gg);
        float hh = sigm_a(go)*tanh_a(c_reg);

        if (step + 1 < Tn){
            *reinterpret_cast<__nv_bfloat16*>(sm + OFF_S + bb*64 + uu*2)
                = __float2bfloat16_rn(hh);
            __syncthreads();

            {
                int rr = tid >> 5;
                int j  = tid & 31;
                int sb2 = j >> 2;
                int gq  = j & 3;
                u64 w0 = *reinterpret_cast<const u64*>(sm + OFF_S + sb2*64 + gq*16);
                u64 w1 = *reinterpret_cast<const u64*>(sm + OFF_S + sb2*64 + gq*16 + 8);
                uint32_t la = smb + OFF_H + (uint32_t)q*HPH
                            + sb2*(HSTR*2) + (u0<<1) + (gq<<4);
                uint32_t ra;
                asm volatile("mapa.shared::cluster.u32 %0, %1, %2;"
                             : "=r"(ra) : "r"(la), "r"(rr));
                asm volatile("st.shared::cluster.b64 [%0], %1;" :: "r"(ra),   "l"(w0));
                asm volatile("st.shared::cluster.b64 [%0], %1;" :: "r"(ra+8), "l"(w1));
            }
            __syncthreads();

            if (tid < 8){
                uint32_t la = smb + OFF_MB + (uint32_t)q*8;
                uint32_t ra;
                asm volatile("mapa.shared::cluster.u32 %0, %1, %2;"
                             : "=r"(ra) : "r"(la), "r"(tid));
                asm volatile("mbarrier.arrive.release.cluster.shared::cluster.b64 _, [%0];"
                             :: "r"(ra) : "memory");
            }

            if (layer == 0){
                g_xh[((size_t)bglob*Tn + t)*HIDn + dir*Hn + u0 + uu]
                    = __float2bfloat16_rn(hh);
            } else {
                g_xA[((size_t)bglob*Tn + t)*HIDn + dir*Hn + u0 + uu] = hh;
            }

            {
                uint32_t mba = smb + OFF_MB + (uint32_t)q*8;
                uint32_t parity = q ? ph1 : ph0;
                asm volatile(
                    "{\n\t.reg .pred P;\n\t"
                    "LW%=:\n\t"
                    "mbarrier.try_wait.parity.acquire.cluster.shared::cta.b64 P, [%0], %1, 0x989680;\n\t"
                    "@P bra LD%=;\n\t"
                    "bra LW%=;\n\t"
                    "LD%=:\n\t}"
                    :: "r"(mba), "r"(parity) : "memory");
                if (q) ph1 ^= 1; else ph0 ^= 1;
            }
        } else {
            if (layer == 0){
                g_xh[((size_t)bglob*Tn + t)*HIDn + dir*Hn + u0 + uu]
                    = __float2bfloat16_rn(hh);
            } else {
                g_xA[((size_t)bglob*Tn + t)*HIDn + dir*Hn + u0 + uu] = hh;
            }
        }

        xgi = ngi; xgf = ngf; xgg = ngg; xgo = ngo;
    }
}

// ---------------------------------------------------------------------------
// Logits: logits[bt][l] = x[bt][:] . cls_w[l][:] + cls_b[l]   (warp per row)
// ---------------------------------------------------------------------------
__global__ __launch_bounds__(256)
void logits_kernel(const float* __restrict__ cls_w, const float* __restrict__ cls_b){
    int row  = (blockIdx.x << 3) + (threadIdx.x >> 5);
    int lane = threadIdx.x & 31;
    const float* xr = g_xA + (size_t)row*HIDn + lane*16;
    float xv[16];
    #pragma unroll
    for (int q=0;q<4;q++){
        float4 v = *reinterpret_cast<const float4*>(xr + q*4);
        xv[q*4+0]=v.x; xv[q*4+1]=v.y; xv[q*4+2]=v.z; xv[q*4+3]=v.w;
    }
    float myout = 0.f;
    #pragma unroll
    for (int l=0;l<NLn;l++){
        const float* wr = cls_w + l*HIDn + lane*16;
        float p = 0.f;
        #pragma unroll
        for (int j=0;j<16;j++) p = fmaf(xv[j], __ldg(wr+j), p);
        #pragma unroll
        for (int o=16;o;o>>=1) p += __shfl_xor_sync(0xffffffffu, p, o);
        if (lane == l) myout = p + cls_b[l];
    }
    if (lane < NLn) g_logits[(size_t)row*NLn + lane] = myout;
}

// ---------------------------------------------------------------------------
// CRF: one warp per batch element. lanes 0..8 hold states.
// ---------------------------------------------------------------------------
__global__ void crf_kernel(const int* __restrict__ labels,
                           const float* __restrict__ start_trans,
                           const float* __restrict__ end_trans,
                           const float* __restrict__ trans){
    int b    = blockIdx.x;
    int lane = threadIdx.x;
    __shared__ float tr_s[NLn*NLn];
    for (int i = lane; i < NLn*NLn; i += 32) tr_s[i] = trans[i];
    __syncwarp();

    bool act = lane < NLn;
    float tr[NLn];
    #pragma unroll
    for (int k=0;k<NLn;k++) tr[k] = act ? trans[k*NLn + lane] : 0.f;

    const float* lg = g_logits + (size_t)b*Tn*NLn;
    const int*   lb = labels   + (size_t)b*Tn;

    float em    = act ? lg[lane] : -1e30f;
    float alpha = act ? (start_trans[lane] + em) : -1e30f;
    int prev = lb[0];
    float num = __shfl_sync(0xffffffffu, em, prev) + start_trans[prev];

    for (int t=1;t<Tn;t++){
        em = act ? lg[t*NLn + lane] : -1e30f;
        int tag = lb[t];
        float v[NLn], m = -1e30f;
        #pragma unroll
        for (int k=0;k<NLn;k++){
            float ak = __shfl_sync(0xffffffffu, alpha, k);
            v[k] = ak + tr[k];
            m = fmaxf(m, v[k]);
        }
        float s = 0.f;
        #pragma unroll
        for (int k=0;k<NLn;k++) s += __expf(v[k]-m);
        float na = m + __logf(s) + em;
        num += tr_s[prev*NLn + tag] + __shfl_sync(0xffffffffu, em, tag);
        alpha = act ? na : -1e30f;
        prev = tag;
    }
    float fa = act ? (alpha + end_trans[lane]) : -1e30f;
    float m = fa;
    #pragma unroll
    for (int o=16;o;o>>=1) m = fmaxf(m, __shfl_xor_sync(0xffffffffu, m, o));
    float s = act ? __expf(fa - m) : 0.f;
    #pragma unroll
    for (int o=16;o;o>>=1) s += __shfl_xor_sync(0xffffffffu, s, o);
    float denom = m + __logf(s);
    num += end_trans[prev];
    if (lane == 0) g_crf[b] = num - denom;
}

__global__ void finish_kernel(float* out){
    int lane = threadIdx.x;
    float s = g_crf[lane] + g_crf[lane+32];
    #pragma unroll
    for (int o=16;o;o>>=1) s += __shfl_xor_sync(0xffffffffu, s, o);
    if (lane == 0) out[0] = -s;
}

// ---------------------------------------------------------------------------
extern "C" void kernel_launch(void* const* d_in, const int* in_sizes, int n_in,
                              void* d_out, int out_size){
    const int*   ids         = (const int*)  d_in[0];
    const int*   labels      = (const int*)  d_in[1];
    const float* emb         = (const float*)d_in[2];
    const float* w_ih        = (const float*)d_in[3];
    const float* w_hh        = (const float*)d_in[4];
    const float* b_ih        = (const float*)d_in[5];
    const float* b_hh        = (const float*)d_in[6];
    const float* cls_w       = (const float*)d_in[7];
    const float* cls_b       = (const float*)d_in[8];
    const float* start_trans = (const float*)d_in[9];
    const float* end_trans   = (const float*)d_in[10];
    const float* trans       = (const float*)d_in[11];
    float* out = (float*)d_out;

    cudaFuncSetAttribute(lstm_cluster_kernel,
                         cudaFuncAttributeMaxDynamicSharedMemorySize, LSTM_SMEM);
    cudaFuncSetAttribute(gemm_xp_mma,
                         cudaFuncAttributeMaxDynamicSharedMemorySize, GSM_TOTAL);

    embed_kernel<<<BTn,128>>>(ids, emb);

    for (int layer = 0; layer < 2; ++layer){
        conv_w_kernel<<<(2048*HIDn)/2048, 256>>>(w_ih + (size_t)layer*2048*HIDn);
        gemm_xp_mma<<<dim3(16,256),128,GSM_TOTAL>>>(
            b_ih + (size_t)layer*2048,
            b_hh + (size_t)layer*2048);
        lstm_cluster_kernel<<<128,256,LSTM_SMEM>>>(layer,
            w_hh + (size_t)layer*2*G4n*Hn);
    }

    logits_kernel<<<BTn/8,256>>>(cls_w, cls_b);
    crf_kernel<<<Bn,32>>>(labels, start_trans, end_trans, trans);
    finish_kernel<<<1,32>>>(out);
}

// round 17
// speedup vs baseline: 1.4582x; 1.0719x over previous
#include <cuda_runtime.h>
#include <cuda_bf16.h>
#include <math.h>
#include <stdint.h>

// ---------------------------------------------------------------------------
// Problem constants
// ---------------------------------------------------------------------------
#define Bn    64
#define Tn    512
#define HIDn  512
#define Hn    256
#define G4n   1024           // 4*H
#define NLn   9
#define BTn   (Bn*Tn)        // 32768

typedef unsigned long long u64;

// ---------------------------------------------------------------------------
// Device scratch (cudaMalloc forbidden -> module globals)
// ---------------------------------------------------------------------------
__device__ float g_xA[BTn*HIDn];                  // 64 MB  (final layer output, fp32)
__device__ __nv_bfloat16 g_xh[BTn*HIDn];          // 32 MB  (bf16 GEMM A: emb / layer-0 h)
__device__ __nv_bfloat16 g_wh[2048*HIDn];         //  2 MB  (bf16 GEMM B = W_ih layer)
__device__ float g_xp[2ll*BTn*G4n];               // 256 MB [dir][bt][gate-row]
__device__ float g_logits[BTn*NLn];
__device__ float g_crf[Bn];

// ---------------------------------------------------------------------------
__device__ __forceinline__ float tanh_a(float x){
    float y; asm("tanh.approx.f32 %0, %1;" : "=f"(y) : "f"(x)); return y;
}
__device__ __forceinline__ float sigm_a(float x){
    return fmaf(0.5f, tanh_a(0.5f*x), 0.5f);
}

#define CP16(d, s) asm volatile("cp.async.cg.shared.global [%0], [%1], 16;" :: "r"(d), "l"(s))
#define CP_COMMIT() asm volatile("cp.async.commit_group;")

// ---------------------------------------------------------------------------
// Embedding gather directly to bf16: g_xh[bt][:] = bf16(emb[ids[bt]][:])
// ---------------------------------------------------------------------------
__global__ void embed_kernel(const int* __restrict__ ids,
                             const float* __restrict__ emb){
    int bt = blockIdx.x;
    int id = ids[bt];
    float4 v = reinterpret_cast<const float4*>(emb + (size_t)id * HIDn)[threadIdx.x];
    __nv_bfloat162 o0 = __floats2bfloat162_rn(v.x, v.y);
    __nv_bfloat162 o1 = __floats2bfloat162_rn(v.z, v.w);
    uint2 pk = make_uint2(*reinterpret_cast<uint32_t*>(&o0),
                          *reinterpret_cast<uint32_t*>(&o1));
    *reinterpret_cast<uint2*>(g_xh + (size_t)bt*HIDn + threadIdx.x*4) = pk;
}

// ---------------------------------------------------------------------------
// fp32 -> bf16 weight convert
// ---------------------------------------------------------------------------
__global__ __launch_bounds__(256)
void conv_w_kernel(const float* __restrict__ W){
    size_t i = (((size_t)blockIdx.x << 8) + threadIdx.x) << 3;
    float4 v0 = *reinterpret_cast<const float4*>(W + i);
    float4 v1 = *reinterpret_cast<const float4*>(W + i + 4);
    __nv_bfloat162 o[4];
    o[0] = __floats2bfloat162_rn(v0.x, v0.y);
    o[1] = __floats2bfloat162_rn(v0.z, v0.w);
    o[2] = __floats2bfloat162_rn(v1.x, v1.y);
    o[3] = __floats2bfloat162_rn(v1.z, v1.w);
    *reinterpret_cast<uint4*>(g_wh + i) = *reinterpret_cast<uint4*>(o);
}

// ---------------------------------------------------------------------------
// Input projection on tensor cores (bf16 mma.sync, fp32 accumulate):
// C(32768 x 2048) = A(32768x512) * W(2048x512)^T ; xp = C + bi + bh.
// EXACT R12 version (verified best): 256 thr, 8 warps 2x4, 64x32 warp tiles,
// cp.async 4-buffer pipeline (issue-ahead 2), one __syncthreads per k-iter.
// ---------------------------------------------------------------------------
#define ASTR 40
#define ABUF 10240
#define GSM_TOTAL (8*ABUF)

__global__ __launch_bounds__(256, 2)
void gemm_xp_mma(const float* __restrict__ bi, const float* __restrict__ bh){
    extern __shared__ __align__(16) char gsm[];
    const uint32_t smb = (uint32_t)__cvta_generic_to_shared(gsm);

    const int tid  = threadIdx.x;
    const int wid  = tid >> 5;
    const int lane = tid & 31;
    const int m0 = blockIdx.y << 7;
    const int n0 = blockIdx.x << 7;
    const int wm = wid >> 2;
    const int wn = wid & 3;

    float acc[4][4][4];
    #pragma unroll
    for (int mi=0;mi<4;mi++)
        #pragma unroll
        for (int ni=0;ni<4;ni++)
            #pragma unroll
            for (int r=0;r<4;r++) acc[mi][ni][r]=0.f;

    const int lrow = tid >> 1;
    const int lqo  = (tid & 1) << 4;
    const __nv_bfloat16* gA = g_xh + (size_t)(m0 + lrow)*HIDn + lqo;
    const __nv_bfloat16* gB = g_wh + (size_t)(n0 + lrow)*HIDn + lqo;
    const uint32_t rowb = lrow*(ASTR*2) + lqo*2;

    uint32_t aRel[4], bRel[4];
    {
        int r16 = lane & 15;
        #pragma unroll
        for (int mi=0;mi<4;mi++)
            aRel[mi] = (((wm<<6) + (mi<<4) + r16)*ASTR + ((lane>>4) << 3)) * 2;
        #pragma unroll
        for (int ni=0;ni<4;ni++)
            bRel[ni] = (((wn<<5) + (ni<<3) + (r16 & 7))*ASTR + (((r16>>3)&1) << 3)) * 2;
    }

    #pragma unroll
    for (int s = 0; s < 2; ++s){
        uint32_t da = smb + (s&3)*ABUF + rowb;
        uint32_t db = smb + 4*ABUF + (s&3)*ABUF + rowb;
        const __nv_bfloat16* sa = gA + s*32;
        const __nv_bfloat16* sb = gB + s*32;
        CP16(da, sa); CP16(da+16, sa+8);
        CP16(db, sb); CP16(db+16, sb+8);
        CP_COMMIT();
    }

    for (int it = 0; it < 16; ++it){
        if (it < 14){
            int s = it + 2;
            uint32_t da = smb + (s&3)*ABUF + rowb;
            uint32_t db = smb + 4*ABUF + (s&3)*ABUF + rowb;
            const __nv_bfloat16* sa = gA + s*32;
            const __nv_bfloat16* sb = gB + s*32;
            CP16(da, sa); CP16(da+16, sa+8);
            CP16(db, sb); CP16(db+16, sb+8);
            CP_COMMIT();
            asm volatile("cp.async.wait_group 2;");
        } else {
            asm volatile("cp.async.wait_group 0;");
        }
        __syncthreads();

        const uint32_t aBase = smb + (it&3)*ABUF;
        const uint32_t bBase = smb + 4*ABUF + (it&3)*ABUF;
        #pragma unroll
        for (int kk = 0; kk < 2; ++kk){
            uint32_t af[4][4];
            #pragma unroll
            for (int mi=0;mi<4;mi++){
                asm volatile("ldmatrix.sync.aligned.m8n8.x4.shared.b16 "
                    "{%0,%1,%2,%3}, [%4];"
                    : "=r"(af[mi][0]),"=r"(af[mi][1]),"=r"(af[mi][2]),"=r"(af[mi][3])
                    : "r"(aBase + aRel[mi] + kk*32));
            }
            uint32_t bfr[4][2];
            #pragma unroll
            for (int ni=0;ni<4;ni++){
                asm volatile("ldmatrix.sync.aligned.m8n8.x2.shared.b16 "
                    "{%0,%1}, [%2];"
                    : "=r"(bfr[ni][0]),"=r"(bfr[ni][1])
                    : "r"(bBase + bRel[ni] + kk*32));
            }
            #pragma unroll
            for (int mi=0;mi<4;mi++){
                #pragma unroll
                for (int ni=0;ni<4;ni++){
                    asm volatile(
                        "mma.sync.aligned.m16n8k16.row.col.f32.bf16.bf16.f32 "
                        "{%0,%1,%2,%3}, {%4,%5,%6,%7}, {%8,%9}, {%0,%1,%2,%3};"
                        : "+f"(acc[mi][ni][0]),"+f"(acc[mi][ni][1]),
                          "+f"(acc[mi][ni][2]),"+f"(acc[mi][ni][3])
                        : "r"(af[mi][0]),"r"(af[mi][1]),"r"(af[mi][2]),"r"(af[mi][3]),
                          "r"(bfr[ni][0]),"r"(bfr[ni][1]));
                }
            }
        }
    }

    const int dir = n0 >> 10;
    #pragma unroll
    for (int ni=0;ni<4;ni++){
        int ncol = n0 + (wn<<5) + (ni<<3) + ((lane & 3) << 1);
        float bs0 = bi[ncol]   + bh[ncol];
        float bs1 = bi[ncol+1] + bh[ncol+1];
        int g = ncol & 1023;
        #pragma unroll
        for (int mi=0;mi<4;mi++){
            int mrow = m0 + (wm<<6) + (mi<<4) + (lane >> 2);
            float2 v0 = make_float2(acc[mi][ni][0] + bs0, acc[mi][ni][1] + bs1);
            float2 v1 = make_float2(acc[mi][ni][2] + bs0, acc[mi][ni][3] + bs1);
            *reinterpret_cast<float2*>(&g_xp[((size_t)dir*BTn + mrow)*G4n + g])   = v0;
            *reinterpret_cast<float2*>(&g_xp[((size_t)dir*BTn + mrow+8)*G4n + g]) = v1;
        }
    }
}

// ---------------------------------------------------------------------------
// Cluster-based persistent bidirectional LSTM.
// R16 = R12 + warp-autonomous h-exchange:
//   - each warp shuffle-packs its own batch row (bf16 pairs -> 8B groups) and
//     pushes directly to all 8 ranks, then arrives per-warp (barrier count 64)
//   - removes STAGE buffer + 2 of 3 per-step __syncthreads (gs anti-dep is
//     subsumed by the step-end mbarrier wait: passing it implies all local
//     warps arrived, i.e. finished reading gs)
// Smem: WSTG[128][264]bf16 @0 | HBUF[2][8][264]bf16 @67584 | GS[128][9]f32
// @76032 | MB[2] @81152
// ---------------------------------------------------------------------------
#define HSTR 264
#define OFF_W 0
#define OFF_H 67584
#define OFF_G 76032
#define OFF_MB 81152
#define LSTM_SMEM 81280
#define HPH 4224

__global__ __launch_bounds__(256, 1) __cluster_dims__(8, 1, 1)
void lstm_cluster_kernel(int layer, const float* __restrict__ whh){
    extern __shared__ __align__(16) char sm[];

    const int tid  = threadIdx.x;
    const int wid  = tid >> 5;
    const int lane = tid & 31;
    const int rank = blockIdx.x & 7;
    const int cid  = blockIdx.x >> 3;
    const int dir  = cid & 1;
    const int bgrp = cid >> 1;
    const int u0   = rank << 5;

    const uint32_t smb = (uint32_t)__cvta_generic_to_shared(sm);

    // stage W_hh (fp32->bf16) into smem: row r = gate*32+uu
    for (int idx = tid; idx < 128*64; idx += 256){
        int r  = idx >> 6;
        int kq = (idx & 63) << 2;
        int grow = dir*G4n + (r>>5)*Hn + u0 + (r&31);
        float4 v = *reinterpret_cast<const float4*>(whh + (size_t)grow*Hn + kq);
        __nv_bfloat162 o0 = __floats2bfloat162_rn(v.x, v.y);
        __nv_bfloat162 o1 = __floats2bfloat162_rn(v.z, v.w);
        uint2 pk = make_uint2(*reinterpret_cast<uint32_t*>(&o0),
                              *reinterpret_cast<uint32_t*>(&o1));
        *reinterpret_cast<uint2*>(sm + OFF_W + r*(HSTR*2) + kq*2) = pk;
    }
    for (int i = tid; i < 2*8*HSTR; i += 256)
        *reinterpret_cast<__nv_bfloat16*>(sm + OFF_H + i*2) = __nv_bfloat16(0.f);

    // 2 step mbarriers, count = 64 (8 CTAs x 8 warps arrive individually)
    if (tid == 0){
        asm volatile("mbarrier.init.shared.b64 [%0], %1;" :: "r"(smb+OFF_MB),   "r"(64) : "memory");
        asm volatile("mbarrier.init.shared.b64 [%0], %1;" :: "r"(smb+OFF_MB+8), "r"(64) : "memory");
    }
    __syncthreads();

    // preload W fragments into registers: warp w -> gate rows 16w..16w+15
    uint32_t afr[16][4];
    {
        uint32_t aAddr = smb + OFF_W + (wid*16 + (lane & 15))*(HSTR*2)
                       + (((lane >> 4) << 3) << 1);
        #pragma unroll
        for (int kk = 0; kk < 16; ++kk){
            asm volatile("ldmatrix.sync.aligned.m8n8.x4.shared.b16 "
                "{%0,%1,%2,%3}, [%4];"
                : "=r"(afr[kk][0]),"=r"(afr[kk][1]),"=r"(afr[kk][2]),"=r"(afr[kk][3])
                : "r"(aAddr + kk*32));
        }
    }

    const int r16 = lane & 15;
    const uint32_t bBase = smb + OFF_H + (r16 & 7)*(HSTR*2) + (((r16>>3)&1) << 4);

    const int bb = tid >> 5;          // elementwise batch (per-warp constant)
    const int uu = tid & 31;          // elementwise unit (consecutive in warp)
    const int bglob = (bgrp << 3) + bb;
    float c_reg = 0.f;

    float* gs = reinterpret_cast<float*>(sm + OFF_G);
    const int grow0 = wid*16 + (lane >> 2);
    const int gcol0 = (lane & 3) << 1;

    // h zero + mbarrier init visible cluster-wide before any remote traffic
    asm volatile("barrier.cluster.arrive.aligned;" ::: "memory");
    asm volatile("barrier.cluster.wait.aligned;"   ::: "memory");

    const float* xp0 = g_xp + ((size_t)dir*BTn + (size_t)bglob*Tn)*G4n + u0 + uu;
    float xgi, xgf, xgg, xgo;
    {
        const float* x = xp0 + (size_t)(dir ? (Tn-1) : 0)*G4n;
        xgi = __ldcs(x); xgf = __ldcs(x+256); xgg = __ldcs(x+512); xgo = __ldcs(x+768);
    }

    int ph0 = 0, ph1 = 0;

    for (int step = 0; step < Tn; ++step){
        const int t = dir ? (Tn-1-step) : step;
        const int p = step & 1;
        const int q = p ^ 1;

        float ngi=0.f, ngf=0.f, ngg=0.f, ngo=0.f;
        if (step+1 < Tn){
            const float* x = xp0 + (size_t)(dir ? (Tn-2-step) : (step+1))*G4n;
            ngi = __ldcs(x); ngf = __ldcs(x+256); ngg = __ldcs(x+512); ngo = __ldcs(x+768);
        }

        // gates = W(regs) @ h(smem): batch ALL 16 ldmatrix, then 16 mmas
        float d[4][4];
        #pragma unroll
        for (int j=0;j<4;j++){ d[j][0]=0.f; d[j][1]=0.f; d[j][2]=0.f; d[j][3]=0.f; }
        {
            const uint32_t bA = bBase + (uint32_t)p*HPH;
            uint32_t bfrag[16][2];
            #pragma unroll
            for (int kk = 0; kk < 16; ++kk){
                asm volatile("ldmatrix.sync.aligned.m8n8.x2.shared.b16 "
                    "{%0,%1}, [%2];" : "=r"(bfrag[kk][0]),"=r"(bfrag[kk][1])
                    : "r"(bA + kk*32));
            }
            #pragma unroll
            for (int kk = 0; kk < 16; ++kk){
                float* dj = d[kk & 3];
                asm volatile(
                    "mma.sync.aligned.m16n8k16.row.col.f32.bf16.bf16.f32 "
                    "{%0,%1,%2,%3}, {%4,%5,%6,%7}, {%8,%9}, {%0,%1,%2,%3};"
                    : "+f"(dj[0]),"+f"(dj[1]),"+f"(dj[2]),"+f"(dj[3])
                    : "r"(afr[kk][0]),"r"(afr[kk][1]),"r"(afr[kk][2]),"r"(afr[kk][3]),
                      "r"(bfrag[kk][0]),"r"(bfrag[kk][1]));
            }
        }
        gs[grow0*9     + gcol0]     = (d[0][0]+d[1][0]) + (d[2][0]+d[3][0]);
        gs[grow0*9     + gcol0 + 1] = (d[0][1]+d[1][1]) + (d[2][1]+d[3][1]);
        gs[(grow0+8)*9 + gcol0]     = (d[0][2]+d[1][2]) + (d[2][2]+d[3][2]);
        gs[(grow0+8)*9 + gcol0 + 1] = (d[0][3]+d[1][3]) + (d[2][3]+d[3][3]);
        __syncthreads();

        float gi = gs[uu*9      + bb] + xgi;
        float gf = gs[(32+uu)*9 + bb] + xgf;
        float gg = gs[(64+uu)*9 + bb] + xgg;
        float go = gs[(96+uu)*9 + bb] + xgo;
        c_reg = sigm_a(gf)*c_reg + sigm_a(gi)*tanh_a(gg);
        float hh = sigm_a(go)*tanh_a(c_reg);

        if (step + 1 < Tn){
            // shuffle-pack this warp's batch row: bf16 pairs -> 8B per 4 units
            uint32_t hv = (uint32_t)__bfloat16_as_ushort(__float2bfloat16_rn(hh));
            uint32_t o1 = __shfl_xor_sync(0xffffffffu, hv, 1);
            uint32_t v32 = ((uu & 1) == 0) ? (hv | (o1 << 16)) : (o1 | (hv << 16));
            uint32_t o2 = __shfl_xor_sync(0xffffffffu, v32, 2);
            u64 v64 = ((uu & 2) == 0) ? ((u64)v32 | ((u64)o2 << 32))
                                      : ((u64)o2 | ((u64)v32 << 32));
            if ((uu & 3) == 0){
                uint32_t la = smb + OFF_H + (uint32_t)q*HPH
                            + bb*(HSTR*2) + ((u0 + uu) << 1);
                #pragma unroll
                for (int rr = 0; rr < 8; ++rr){
                    uint32_t ra;
                    asm volatile("mapa.shared::cluster.u32 %0, %1, %2;"
                                 : "=r"(ra) : "r"(la), "r"(rr));
                    asm volatile("st.shared::cluster.b64 [%0], %1;"
                                 :: "r"(ra), "l"(v64));
                }
            }
            __syncwarp();

            // per-warp arrive (release) on every rank's mb[q]
            if (uu < 8){
                uint32_t la = smb + OFF_MB + (uint32_t)q*8;
                uint32_t ra;
                asm volatile("mapa.shared::cluster.u32 %0, %1, %2;"
                             : "=r"(ra) : "r"(la), "r"(uu));
                asm volatile("mbarrier.arrive.release.cluster.shared::cluster.b64 _, [%0];"
                             :: "r"(ra) : "memory");
            }

            // global h store overlaps the wait
            if (layer == 0){
                g_xh[((size_t)bglob*Tn + t)*HIDn + dir*Hn + u0 + uu]
                    = __float2bfloat16_rn(hh);
            } else {
                g_xA[((size_t)bglob*Tn + t)*HIDn + dir*Hn + u0 + uu] = hh;
            }

            // wait (acquire) on local mb[q]
            {
                uint32_t mba = smb + OFF_MB + (uint32_t)q*8;
                uint32_t parity = q ? ph1 : ph0;
                asm volatile(
                    "{\n\t.reg .pred P;\n\t"
                    "LW%=:\n\t"
                    "mbarrier.try_wait.parity.acquire.cluster.shared::cta.b64 P, [%0], %1, 0x989680;\n\t"
                    "@P bra LD%=;\n\t"
                    "bra LW%=;\n\t"
                    "LD%=:\n\t}"
                    :: "r"(mba), "r"(parity) : "memory");
                if (q) ph1 ^= 1; else ph0 ^= 1;
            }
        } else {
            if (layer == 0){
                g_xh[((size_t)bglob*Tn + t)*HIDn + dir*Hn + u0 + uu]
                    = __float2bfloat16_rn(hh);
            } else {
                g_xA[((size_t)bglob*Tn + t)*HIDn + dir*Hn + u0 + uu] = hh;
            }
        }

        xgi = ngi; xgf = ngf; xgg = ngg; xgo = ngo;
    }
}

// ---------------------------------------------------------------------------
// Logits: logits[bt][l] = x[bt][:] . cls_w[l][:] + cls_b[l]   (warp per row)
// ---------------------------------------------------------------------------
__global__ __launch_bounds__(256)
void logits_kernel(const float* __restrict__ cls_w, const float* __restrict__ cls_b){
    int row  = (blockIdx.x << 3) + (threadIdx.x >> 5);
    int lane = threadIdx.x & 31;
    const float* xr = g_xA + (size_t)row*HIDn + lane*16;
    float xv[16];
    #pragma unroll
    for (int q=0;q<4;q++){
        float4 v = *reinterpret_cast<const float4*>(xr + q*4);
        xv[q*4+0]=v.x; xv[q*4+1]=v.y; xv[q*4+2]=v.z; xv[q*4+3]=v.w;
    }
    float myout = 0.f;
    #pragma unroll
    for (int l=0;l<NLn;l++){
        const float* wr = cls_w + l*HIDn + lane*16;
        float p = 0.f;
        #pragma unroll
        for (int j=0;j<16;j++) p = fmaf(xv[j], __ldg(wr+j), p);
        #pragma unroll
        for (int o=16;o;o>>=1) p += __shfl_xor_sync(0xffffffffu, p, o);
        if (lane == l) myout = p + cls_b[l];
    }
    if (lane < NLn) g_logits[(size_t)row*NLn + lane] = myout;
}

// ---------------------------------------------------------------------------
// CRF: one warp per batch element. lanes 0..8 hold states.
// ---------------------------------------------------------------------------
__global__ void crf_kernel(const int* __restrict__ labels,
                           const float* __restrict__ start_trans,
                           const float* __restrict__ end_trans,
                           const float* __restrict__ trans){
    int b    = blockIdx.x;
    int lane = threadIdx.x;
    __shared__ float tr_s[NLn*NLn];
    for (int i = lane; i < NLn*NLn; i += 32) tr_s[i] = trans[i];
    __syncwarp();

    bool act = lane < NLn;
    float tr[NLn];
    #pragma unroll
    for (int k=0;k<NLn;k++) tr[k] = act ? trans[k*NLn + lane] : 0.f;

    const float* lg = g_logits + (size_t)b*Tn*NLn;
    const int*   lb = labels   + (size_t)b*Tn;

    float em    = act ? lg[lane] : -1e30f;
    float alpha = act ? (start_trans[lane] + em) : -1e30f;
    int prev = lb[0];
    float num = __shfl_sync(0xffffffffu, em, prev) + start_trans[prev];

    for (int t=1;t<Tn;t++){
        em = act ? lg[t*NLn + lane] : -1e30f;
        int tag = lb[t];
        float v[NLn], m = -1e30f;
        #pragma unroll
        for (int k=0;k<NLn;k++){
            float ak = __shfl_sync(0xffffffffu, alpha, k);
            v[k] = ak + tr[k];
            m = fmaxf(m, v[k]);
        }
        float s = 0.f;
        #pragma unroll
        for (int k=0;k<NLn;k++) s += __expf(v[k]-m);
        float na = m + __logf(s) + em;
        num += tr_s[prev*NLn + tag] + __shfl_sync(0xffffffffu, em, tag);
        alpha = act ? na : -1e30f;
        prev = tag;
    }
    float fa = act ? (alpha + end_trans[lane]) : -1e30f;
    float m = fa;
    #pragma unroll
    for (int o=16;o;o>>=1) m = fmaxf(m, __shfl_xor_sync(0xffffffffu, m, o));
    float s = act ? __expf(fa - m) : 0.f;
    #pragma unroll
    for (int o=16;o;o>>=1) s += __shfl_xor_sync(0xffffffffu, s, o);
    float denom = m + __logf(s);
    num += end_trans[prev];
    if (lane == 0) g_crf[b] = num - denom;
}

__global__ void finish_kernel(float* out){
    int lane = threadIdx.x;
    float s = g_crf[lane] + g_crf[lane+32];
    #pragma unroll
    for (int o=16;o;o>>=1) s += __shfl_xor_sync(0xffffffffu, s, o);
    if (lane == 0) out[0] = -s;
}

// ---------------------------------------------------------------------------
extern "C" void kernel_launch(void* const* d_in, const int* in_sizes, int n_in,
                              void* d_out, int out_size){
    const int*   ids         = (const int*)  d_in[0];
    const int*   labels      = (const int*)  d_in[1];
    const float* emb         = (const float*)d_in[2];
    const float* w_ih        = (const float*)d_in[3];
    const float* w_hh        = (const float*)d_in[4];
    const float* b_ih        = (const float*)d_in[5];
    const float* b_hh        = (const float*)d_in[6];
    const float* cls_w       = (const float*)d_in[7];
    const float* cls_b       = (const float*)d_in[8];
    const float* start_trans = (const float*)d_in[9];
    const float* end_trans   = (const float*)d_in[10];
    const float* trans       = (const float*)d_in[11];
    float* out = (float*)d_out;

    cudaFuncSetAttribute(lstm_cluster_kernel,
                         cudaFuncAttributeMaxDynamicSharedMemorySize, LSTM_SMEM);
    cudaFuncSetAttribute(gemm_xp_mma,
                         cudaFuncAttributeMaxDynamicSharedMemorySize, GSM_TOTAL);

    embed_kernel<<<BTn,128>>>(ids, emb);

    for (int layer = 0; layer < 2; ++layer){
        conv_w_kernel<<<(2048*HIDn)/2048, 256>>>(w_ih + (size_t)layer*2048*HIDn);
        gemm_xp_mma<<<dim3(16,256),256,GSM_TOTAL>>>(
            b_ih + (size_t)layer*2048,
            b_hh + (size_t)layer*2048);
        lstm_cluster_kernel<<<128,256,LSTM_SMEM>>>(layer,
            w_hh + (size_t)layer*2*G4n*Hn);
    }

    logits_kernel<<<BTn/8,256>>>(cls_w, cls_b);
    crf_kernel<<<Bn,32>>>(labels, start_trans, end_trans, trans);
    finish_kernel<<<1,32>>>(out);
}